// round 17
// baseline (speedup 1.0000x reference)
#include <cuda_runtime.h>
#include <cuda_fp16.h>
#include <cstdint>

#define LATENT 64
#define OUT    128
#define H      32
#define BM     64    // rows per CTA
#define PITCH  144   // bytes per smem A row (72 fp16) — conflict-free ldmatrix

// smem layout (dynamic): dual constant copies (one per half-CTA) + A tile
#define SM_SP0   0
#define SM_SN0   512
#define SM_B30   1024
#define SM_SP1   1536
#define SM_SN1   2048
#define SM_B31   2560
#define SM_AHI   3072
#define SM_TOTAL (SM_AHI + BM * PITCH)   // 12288

// Scratch (no device allocation allowed)
__device__ float g_sp[OUT];
__device__ float g_sn[OUT];
__device__ int   g_slow = 0;
// B mma fragments, fp16, PERMUTED feature->column mapping (see precompute):
// u32 index = (((wn*4+g)*4+s)*32 + flane)*2 + reg
__device__ __align__(16) uint32_t g_bf[4 * 4 * 4 * 32 * 2];

// ---------------------------------------------------------------------------
// PTX helpers (family-portable only: ldmatrix + mma.sync)
// ---------------------------------------------------------------------------
__device__ __forceinline__ uint32_t smem_u32(const void* p) {
    uint32_t a;
    asm("{ .reg .u64 t; cvta.to.shared.u64 t, %1; cvt.u32.u64 %0, t; }"
        : "=r"(a) : "l"(p));
    return a;
}
#define LDSM_X4(r0, r1, r2, r3, addr)                                          \
    asm volatile("ldmatrix.sync.aligned.m8n8.x4.shared.b16 {%0,%1,%2,%3}, [%4];" \
                 : "=r"(r0), "=r"(r1), "=r"(r2), "=r"(r3) : "r"(addr))
#define MMA_F16(c, a, b)                                                       \
    asm volatile("mma.sync.aligned.m16n8k16.row.col.f32.f16.f16.f32 "          \
                 "{%0,%1,%2,%3},{%4,%5,%6,%7},{%8,%9},{%0,%1,%2,%3};"          \
                 : "+f"((c)[0]), "+f"((c)[1]), "+f"((c)[2]), "+f"((c)[3])      \
                 : "r"((a)[0]), "r"((a)[1]), "r"((a)[2]), "r"((a)[3]),         \
                   "r"((b)[0]), "r"((b)[1]))

__device__ __forceinline__ uint32_t pack_h2(float a, float b) {
    __half2 h = __floats2half2_rn(a, b);
    return *(uint32_t*)&h;
}

// ---------------------------------------------------------------------------
// Precompute (one block per feature d, 128 threads = 4 warps):
//  - collapsed slopes sp/sn, 4x parallel over k-rows of W2
//  - fp16 B fragments of |Wp| with PERMUTED feature->column mapping:
//      tile g = (d>>1)&3, n-pos nb = 2*((d>>3)&3) + (d&1)
//    => epilogue thread (lane&3)=p owns contiguous cols wn*32 + p*8 + 0..7.
// ---------------------------------------------------------------------------
__global__ void precompute_kernel(const float* __restrict__ Wp,
                                  const float* __restrict__ W1,
                                  const float* __restrict__ b1,
                                  const float* __restrict__ W2,
                                  const float* __restrict__ b2,
                                  const float* __restrict__ W3)
{
    const int d    = blockIdx.x;
    const int tid  = threadIdx.x;     // 0..127
    const int w    = tid >> 5;        // warp 0..3 -> k-rows w*8..w*8+7
    const int lane = tid & 31;
    const int row  = (w << 3) + (lane >> 2);   // k-row 0..31
    const int q    = lane & 3;                 // h-quarter (8 elems)

    __shared__ float redp[4], redn[4];

    // Issue all loads up front
    const float4* w2p = (const float4*)(W2 + ((long)d * H + row) * H + q * 8);
    float4 a0 = w2p[0], a1 = w2p[1];
    const float4* w1p = (const float4*)(W1 + d * H + q * 8);
    float4 h0 = w1p[0], h1 = w1p[1];
    float  w3 = W3[d * H + row];

    // B fragments (warp 0, lanes 0-15): permuted-d mma B lane layout.
    if (tid < 16) {
        const int s  = lane >> 2;
        const int kq = lane & 3;
        const int k0 = s * 16 + kq * 2;
        float f0 = fabsf(Wp[d * LATENT + k0]);
        float f1 = fabsf(Wp[d * LATENT + k0 + 1]);
        float f2 = fabsf(Wp[d * LATENT + k0 + 8]);
        float f3 = fabsf(Wp[d * LATENT + k0 + 9]);
        const int wn    = d >> 5;
        const int g     = (d >> 1) & 3;                    // permuted tile
        const int nb    = 2 * ((d >> 3) & 3) + (d & 1);    // permuted n-pos
        const int flane = nb * 4 + kq;
        const int idx   = ((((wn * 4 + g) * 4 + s) * 32) + flane) * 2;
        g_bf[idx]     = pack_h2(f0, f1);
        g_bf[idx + 1] = pack_h2(f2, f3);
    }

    // nz check (warp 1: lanes check b1/b2 element `lane`)
    if (w == 1) {
        int nz = (b1[d * H + lane] != 0.f) | (b2[d * H + lane] != 0.f);
        unsigned any_nz = __ballot_sync(0xffffffffu, nz);
        if (lane == 0 && any_nz) atomicOr(&g_slow, 1);
    }

    // Partial dots over 8 h-elements
    float up = 0.f, un = 0.f;
    up = fmaf(a0.x, fmaxf(h0.x, 0.f), up); un = fmaf(a0.x, fmaxf(-h0.x, 0.f), un);
    up = fmaf(a0.y, fmaxf(h0.y, 0.f), up); un = fmaf(a0.y, fmaxf(-h0.y, 0.f), un);
    up = fmaf(a0.z, fmaxf(h0.z, 0.f), up); un = fmaf(a0.z, fmaxf(-h0.z, 0.f), un);
    up = fmaf(a0.w, fmaxf(h0.w, 0.f), up); un = fmaf(a0.w, fmaxf(-h0.w, 0.f), un);
    up = fmaf(a1.x, fmaxf(h1.x, 0.f), up); un = fmaf(a1.x, fmaxf(-h1.x, 0.f), un);
    up = fmaf(a1.y, fmaxf(h1.y, 0.f), up); un = fmaf(a1.y, fmaxf(-h1.y, 0.f), un);
    up = fmaf(a1.z, fmaxf(h1.z, 0.f), up); un = fmaf(a1.z, fmaxf(-h1.z, 0.f), un);
    up = fmaf(a1.w, fmaxf(h1.w, 0.f), up); un = fmaf(a1.w, fmaxf(-h1.w, 0.f), un);

    // Reduce within group of 4 (full row dot at q==0)
    up += __shfl_down_sync(0xffffffffu, up, 2, 4);
    up += __shfl_down_sync(0xffffffffu, up, 1, 4);
    un += __shfl_down_sync(0xffffffffu, un, 2, 4);
    un += __shfl_down_sync(0xffffffffu, un, 1, 4);

    float tp = (q == 0) ? w3 * fmaxf(up, 0.f) : 0.f;
    float tn = (q == 0) ? w3 * fmaxf(un, 0.f) : 0.f;

    // Gather the 8 q==0 lanes (0,4,...,28) to lane 0
    tp += __shfl_down_sync(0xffffffffu, tp, 4);
    tp += __shfl_down_sync(0xffffffffu, tp, 8);
    tp += __shfl_down_sync(0xffffffffu, tp, 16);
    tn += __shfl_down_sync(0xffffffffu, tn, 4);
    tn += __shfl_down_sync(0xffffffffu, tn, 8);
    tn += __shfl_down_sync(0xffffffffu, tn, 16);

    if (lane == 0) { redp[w] = tp; redn[w] = tn; }
    __syncthreads();
    if (tid == 0) {
        g_sp[d] = redp[0] + redp[1] + redp[2] + redp[3];
        g_sn[d] = redn[0] + redn[1] + redn[2] + redn[3];
    }
}

// ---------------------------------------------------------------------------
// Main: single-term fp16 mma.sync GEMM (BM=64 x 128, K=64) + fused epilogue.
// A = rn(z) fp16 via smem+ldmatrix; B fragments fully register-resident.
// Permuted feature mapping -> epilogue writes 2x STG.128 per row per thread.
// Half-CTA named barriers + dual const copies. 8 warps, 3 CTAs/SM.
// ---------------------------------------------------------------------------
__global__ __launch_bounds__(256, 3) void main_kernel(
    const float* __restrict__ z,  const float* __restrict__ Wp,
    const float* __restrict__ W1, const float* __restrict__ b1,
    const float* __restrict__ W2, const float* __restrict__ b2,
    const float* __restrict__ W3, const float* __restrict__ b3,
    float* __restrict__ out, long total)
{
    if (g_slow) {   // exact fallback path (never taken when b1==b2==0)
        for (long idx = (long)blockIdx.x * blockDim.x + threadIdx.x; idx < total;
             idx += (long)gridDim.x * blockDim.x) {
            int n = (int)(idx >> 7);
            int d = (int)(idx & (OUT - 1));
            float y = 0.f;
#pragma unroll
            for (int k = 0; k < LATENT; ++k)
                y = fmaf(z[(long)n * LATENT + k], fabsf(Wp[d * LATENT + k]), y);
            float h1[H];
#pragma unroll
            for (int h = 0; h < H; ++h)
                h1[h] = fmaxf(fmaf(y, W1[d * H + h], b1[d * H + h]), 0.f);
            float x = b3[d];
#pragma unroll 4
            for (int k = 0; k < H; ++k) {
                float t = b2[d * H + k];
                const float* w2 = W2 + ((long)d * H + k) * H;
#pragma unroll
                for (int h = 0; h < H; ++h) t = fmaf(w2[h], h1[h], t);
                x = fmaf(W3[d * H + k], fmaxf(t, 0.f), x);
            }
            out[idx] = fabsf(x);
        }
        return;
    }

    extern __shared__ char smem[];
    const uint32_t sb = smem_u32(smem);
    const int tid  = threadIdx.x;
    const int wid  = tid >> 5;
    const int lane = tid & 31;
    const int wm   = wid >> 2;   // 0..1 -> rows wm*32; also half-CTA id
    const int wn   = wid & 3;    // 0..3 -> cols wn*32
    const int brow = blockIdx.x * BM;

    // z tile loads first (deepest latency): 64 rows x 64 f32.
    const int zrow = tid >> 2;
    const int zseg = tid & 3;
    const float4* zr = (const float4*)(z + (size_t)(brow + zrow) * LATENT + zseg * 16);
    float4 v[4];
#pragma unroll
    for (int j = 0; j < 4; ++j) v[j] = __ldcs(zr + j);

    // B fragments: all 16 loads up front, register-resident (L2/L1-hot).
    // Strides (u32): wn:1024, g:256, s:64, lane:2.
    const uint32_t* bfbase = g_bf + (size_t)wn * 1024 + lane * 2;
    uint32_t bf[4][4][2];   // [s][g][reg]
#pragma unroll
    for (int g = 0; g < 4; ++g)
#pragma unroll
        for (int s = 0; s < 4; ++s) {
            uint2 t = *(const uint2*)(bfbase + g * 256 + s * 64);
            bf[s][g][0] = t.x; bf[s][g][1] = t.y;
        }

    // Stage epilogue constants: one copy per half-CTA (sn sign-folded).
    {
        const int hid  = tid >> 7;            // 0: threads 0-127, 1: 128-255
        const int c    = tid & 127;
        const int base = hid ? SM_SP1 : SM_SP0;
        ((float*)(smem + base))[c]        = g_sp[c];
        ((float*)(smem + base + 512))[c]  = -g_sn[c];
        ((float*)(smem + base + 1024))[c] = b3[c];
    }

    // fp16 convert of z into smem (single term: A = rn(z))
    {
        uint4 uh0, uh1;
        uh0.x = pack_h2(v[0].x, v[0].y); uh0.y = pack_h2(v[0].z, v[0].w);
        uh0.z = pack_h2(v[1].x, v[1].y); uh0.w = pack_h2(v[1].z, v[1].w);
        uh1.x = pack_h2(v[2].x, v[2].y); uh1.y = pack_h2(v[2].z, v[2].w);
        uh1.z = pack_h2(v[3].x, v[3].y); uh1.w = pack_h2(v[3].z, v[3].w);
        int off = zrow * PITCH + zseg * 32;   // 16 floats -> 32 bytes fp16
        *(uint4*)(smem + SM_AHI + off)      = uh0;
        *(uint4*)(smem + SM_AHI + off + 16) = uh1;
    }
    // Half-CTA barrier: warps 0-3 sync with threads 0-127 (rows 0-31),
    // warps 4-7 with threads 128-255 (rows 32-63).
    asm volatile("bar.sync %0, 128;" :: "r"(1 + wm) : "memory");

    // ldmatrix lane base address (A)
    const uint32_t aoff = sb + SM_AHI + (uint32_t)((wm * 32 + (lane & 15)) * PITCH +
                                                   (lane >> 4) * 16);

    float acc[2][4][4];
#pragma unroll
    for (int f = 0; f < 2; ++f)
#pragma unroll
        for (int g = 0; g < 4; ++g)
#pragma unroll
            for (int e = 0; e < 4; ++e) acc[f][g][e] = 0.f;

    // K=64 in 4 k16 steps; B in registers, loop = LDSM + MMA only.
#pragma unroll
    for (int s = 0; s < 4; ++s) {
        uint32_t ah[2][4];
#pragma unroll
        for (int f = 0; f < 2; ++f)
            LDSM_X4(ah[f][0], ah[f][1], ah[f][2], ah[f][3],
                    aoff + f * 16 * PITCH + s * 32);
#pragma unroll
        for (int f = 0; f < 2; ++f)
#pragma unroll
            for (int g = 0; g < 4; ++g)
                MMA_F16(acc[f][g], ah[f], bf[s][g]);
    }

    // Fused epilogue: thread owns 8 contiguous cols dbase..dbase+7.
    // acc[f][g][half*2+j] -> col dbase + 2g + j, row = wm*32+f*16+qrow+half*8.
    {
        const int p     = lane & 3;
        const int qrow  = lane >> 2;
        const int dbase = wn * 32 + p * 8;
        const int cbase = wm ? SM_SP1 : SM_SP0;
        const float* sps = (const float*)(smem + cbase) + dbase;
        const float* sns = (const float*)(smem + cbase + 512) + dbase;  // -sn
        const float* b3s = (const float*)(smem + cbase + 1024) + dbase;
        float spv[8], snv[8], bbv[8];
#pragma unroll
        for (int c = 0; c < 8; ++c) {
            spv[c] = sps[c]; snv[c] = sns[c]; bbv[c] = b3s[c];
        }
#pragma unroll
        for (int f = 0; f < 2; ++f) {
#pragma unroll
            for (int half = 0; half < 2; ++half) {
                const int r = brow + wm * 32 + f * 16 + qrow + half * 8;
                float o[8];
#pragma unroll
                for (int g = 0; g < 4; ++g) {
#pragma unroll
                    for (int j = 0; j < 2; ++j) {
                        const int c = g * 2 + j;
                        float y = acc[f][g][half * 2 + j];
                        o[c] = fabsf(fmaf(y, (y > 0.f ? spv[c] : snv[c]), bbv[c]));
                    }
                }
                float* op = out + (size_t)r * OUT + dbase;
                *(float4*)op       = make_float4(o[0], o[1], o[2], o[3]);
                *(float4*)(op + 4) = make_float4(o[4], o[5], o[6], o[7]);
            }
        }
    }
}

// ---------------------------------------------------------------------------
extern "C" void kernel_launch(void* const* d_in, const int* in_sizes, int n_in,
                              void* d_out, int out_size)
{
    const float* z  = (const float*)d_in[0];
    const float* Wp = (const float*)d_in[1];
    const float* W1 = (const float*)d_in[2];
    const float* b1 = (const float*)d_in[3];
    const float* W2 = (const float*)d_in[4];
    const float* b2 = (const float*)d_in[5];
    const float* W3 = (const float*)d_in[6];
    const float* b3 = (const float*)d_in[7];
    float* out = (float*)d_out;

    int nrows = in_sizes[0] / LATENT;   // 65536

    cudaFuncSetAttribute(main_kernel,
                         cudaFuncAttributeMaxDynamicSharedMemorySize, SM_TOTAL);

    precompute_kernel<<<OUT, 128>>>(Wp, W1, b1, W2, b2, W3);
    main_kernel<<<nrows / BM, 256, SM_TOTAL>>>(z, Wp, W1, b1, W2, b2, W3, b3,
                                               out, (long)nrows * OUT);
}